// round 2
// baseline (speedup 1.0000x reference)
#include <cuda_runtime.h>
#include <cstdint>

#define N_ROWS 4096
#define VOCAB  50000
#define DIM    64

#define BM 128
#define BN 128
#define LDS_STRIDE 68   // floats; 68 % 32 == 4 -> conflict-free quad pattern, 16B aligned
#define SMEM_BYTES (2 * BM * LDS_STRIDE * 4)

// scratch (no allocs allowed -> device globals)
__device__ float g_sums[N_ROWS];
__device__ float g_loss;

__device__ __forceinline__ unsigned f2tf32(float f) {
    unsigned u;
    asm("cvt.rna.tf32.f32 %0, %1;" : "=r"(u) : "f"(f));
    return u;
}

__global__ void init_kernel() {
    int i = blockIdx.x * blockDim.x + threadIdx.x;
    if (i < N_ROWS) g_sums[i] = 0.f;
    if (i == 0) g_loss = 0.f;
}

// PASS 0: logits -> exp -> per-row sum (atomicAdd into g_sums)
// PASS 1: logits -> exp * (1/g_sums[row]) -> write probs
template <int PASS>
__global__ void __launch_bounds__(256, 2)
gemm_softmax_kernel(const float* __restrict__ A,   // [N_ROWS, DIM]
                    const float* __restrict__ B,   // [VOCAB, DIM]
                    float* __restrict__ out)       // [N_ROWS, VOCAB]
{
    extern __shared__ float smem[];
    float* As = smem;                      // BM x LDS_STRIDE (tf32 bit patterns)
    float* Bs = smem + BM * LDS_STRIDE;    // BN x LDS_STRIDE

    const int tid = threadIdx.x;
    const int m0 = blockIdx.y * BM;
    const int v0 = blockIdx.x * BN;

    // ---- load A tile [BM x 64] as tf32 ----
    {
        const float4* Ag = (const float4*)(A + (size_t)m0 * DIM);
        #pragma unroll
        for (int t = 0; t < 8; t++) {
            int i = tid + t * 256;            // 0..2047 float4s
            int row = i >> 4, c4 = i & 15;
            float4 v = Ag[row * 16 + c4];
            uint4 w;
            w.x = f2tf32(v.x); w.y = f2tf32(v.y);
            w.z = f2tf32(v.z); w.w = f2tf32(v.w);
            *(uint4*)&As[row * LDS_STRIDE + c4 * 4] = w;
        }
        #pragma unroll
        for (int t = 0; t < 8; t++) {
            int i = tid + t * 256;
            int row = i >> 4, c4 = i & 15;
            int v = v0 + row;
            float4 val = make_float4(0.f, 0.f, 0.f, 0.f);
            if (v < VOCAB) val = ((const float4*)(B + (size_t)v * DIM))[c4];
            uint4 w;
            w.x = f2tf32(val.x); w.y = f2tf32(val.y);
            w.z = f2tf32(val.z); w.w = f2tf32(val.w);
            *(uint4*)&Bs[row * LDS_STRIDE + c4 * 4] = w;
        }
    }
    __syncthreads();

    const int lane = tid & 31;
    const int wid  = tid >> 5;
    const int wm = wid >> 2;           // 0..1 : 64 rows each
    const int wn = wid & 3;            // 0..3 : 32 cols each
    const int mBase = wm * 64;
    const int nBase = wn * 32;
    const int lr = lane >> 2;          // groupID
    const int lc = lane & 3;           // threadID_in_group

    float c[4][4][4];
    #pragma unroll
    for (int a = 0; a < 4; a++)
        #pragma unroll
        for (int b = 0; b < 4; b++)
            #pragma unroll
            for (int d = 0; d < 4; d++) c[a][b][d] = 0.f;

    // ---- K = 64 = 8 k-steps of m16n8k8 tf32 MMA ----
    #pragma unroll
    for (int k = 0; k < 8; k++) {
        unsigned af[4][4], bf[4][2];
        #pragma unroll
        for (int mf = 0; mf < 4; mf++) {
            const float* base = &As[(mBase + mf * 16 + lr) * LDS_STRIDE + k * 8 + lc];
            af[mf][0] = __float_as_uint(base[0]);
            af[mf][1] = __float_as_uint(base[8 * LDS_STRIDE]);
            af[mf][2] = __float_as_uint(base[4]);
            af[mf][3] = __float_as_uint(base[8 * LDS_STRIDE + 4]);
        }
        #pragma unroll
        for (int nf = 0; nf < 4; nf++) {
            const float* base = &Bs[(nBase + nf * 8 + lr) * LDS_STRIDE + k * 8 + lc];
            bf[nf][0] = __float_as_uint(base[0]);
            bf[nf][1] = __float_as_uint(base[4]);
        }
        #pragma unroll
        for (int mf = 0; mf < 4; mf++)
            #pragma unroll
            for (int nf = 0; nf < 4; nf++) {
                asm volatile(
                    "mma.sync.aligned.m16n8k8.row.col.f32.tf32.tf32.f32 "
                    "{%0,%1,%2,%3}, {%4,%5,%6,%7}, {%8,%9}, {%0,%1,%2,%3};"
                    : "+f"(c[mf][nf][0]), "+f"(c[mf][nf][1]),
                      "+f"(c[mf][nf][2]), "+f"(c[mf][nf][3])
                    : "r"(af[mf][0]), "r"(af[mf][1]), "r"(af[mf][2]), "r"(af[mf][3]),
                      "r"(bf[nf][0]), "r"(bf[nf][1]));
            }
    }

    if (PASS == 0) {
        // ---- per-row sum of exp(logit), masked at tail ----
        __syncthreads();
        if (tid < BM) As[tid] = 0.f;
        __syncthreads();
        #pragma unroll
        for (int mf = 0; mf < 4; mf++) {
            #pragma unroll
            for (int h = 0; h < 2; h++) {
                float s = 0.f;
                #pragma unroll
                for (int nf = 0; nf < 4; nf++) {
                    #pragma unroll
                    for (int j = 0; j < 2; j++) {
                        int col = v0 + nBase + nf * 8 + lc * 2 + j;
                        float e = __expf(c[mf][nf][h * 2 + j]);
                        s += (col < VOCAB) ? e : 0.f;
                    }
                }
                s += __shfl_xor_sync(0xffffffffu, s, 1);
                s += __shfl_xor_sync(0xffffffffu, s, 2);
                if (lc == 0) atomicAdd(&As[mBase + mf * 16 + h * 8 + lr], s);
            }
        }
        __syncthreads();
        if (tid < BM) atomicAdd(&g_sums[m0 + tid], As[tid]);
    } else {
        // ---- write probs = exp(logit) / rowsum ----
        __syncthreads();
        if (tid < BM) As[tid] = 1.0f / g_sums[m0 + tid];
        __syncthreads();
        #pragma unroll
        for (int mf = 0; mf < 4; mf++) {
            #pragma unroll
            for (int h = 0; h < 2; h++) {
                int rl = mBase + mf * 16 + h * 8 + lr;
                float r = As[rl];
                size_t rowOff = (size_t)(m0 + rl) * VOCAB;
                #pragma unroll
                for (int nf = 0; nf < 4; nf++) {
                    int col = v0 + nBase + nf * 8 + lc * 2;
                    if (col < VOCAB) {   // VOCAB even -> pair never straddles the edge
                        float2 p;
                        p.x = __expf(c[mf][nf][h * 2 + 0]) * r;
                        p.y = __expf(c[mf][nf][h * 2 + 1]) * r;
                        *(float2*)(out + rowOff + col) = p;
                    }
                }
            }
        }
    }
}

// loss = mean_n( log(sum_n) - logit_label_n ); clipping never binds (min prob ~2e-6 >> 1e-7)
__global__ void loss_kernel(const int* __restrict__ label_words,
                            const float* __restrict__ inp,
                            const float* __restrict__ emb) {
    int n = blockIdx.x * blockDim.x + threadIdx.x;

    // dtype sniff: int64 labels (values < 2^31) have all odd 32-bit words == 0.
    // int32 labels make that astronomically unlikely (uniform over [0,50000)).
    bool is64 = true;
    #pragma unroll
    for (int i = 0; i < 64; i++) is64 &= (label_words[2 * i + 1] == 0);

    float v = 0.f;
    if (n < N_ROWS) {
        int lab = is64 ? label_words[2 * n] : label_words[n];
        const float4* a = (const float4*)(inp + (size_t)n * DIM);
        const float4* b = (const float4*)(emb + (size_t)lab * DIM);
        float dot = 0.f;
        #pragma unroll
        for (int i = 0; i < DIM / 4; i++) {
            float4 x = a[i], y = b[i];
            dot += x.x * y.x + x.y * y.y + x.z * y.z + x.w * y.w;
        }
        v = logf(g_sums[n]) - dot;
    }
    __shared__ float red[256];
    red[threadIdx.x] = v;
    __syncthreads();
    for (int s = 128; s > 0; s >>= 1) {
        if (threadIdx.x < s) red[threadIdx.x] += red[threadIdx.x + s];
        __syncthreads();
    }
    if (threadIdx.x == 0) atomicAdd(&g_loss, red[0]);
}

__global__ void finalize_kernel(float* out, long long idx) {
    out[idx] = g_loss * (1.0f / (float)N_ROWS);
}

extern "C" void kernel_launch(void* const* d_in, const int* in_sizes, int n_in,
                              void* d_out, int out_size) {
    const int*   label = (const int*)d_in[0];      // int32 or int64 (sniffed in-kernel)
    const float* inp   = (const float*)d_in[1];    // [4096, 64]
    const float* emb   = (const float*)d_in[2];    // [50000, 64]
    float* out = (float*)d_out;                    // [4096*50000] probs + [1] loss

    cudaFuncSetAttribute(gemm_softmax_kernel<0>,
                         cudaFuncAttributeMaxDynamicSharedMemorySize, SMEM_BYTES);
    cudaFuncSetAttribute(gemm_softmax_kernel<1>,
                         cudaFuncAttributeMaxDynamicSharedMemorySize, SMEM_BYTES);

    dim3 grid((VOCAB + BN - 1) / BN, N_ROWS / BM);   // 391 x 32

    init_kernel<<<16, 256>>>();
    gemm_softmax_kernel<0><<<grid, 256, SMEM_BYTES>>>(inp, emb, out);
    loss_kernel<<<N_ROWS / 256, 256>>>(label, inp, emb);
    finalize_kernel<<<1, 1>>>(out, (long long)out_size - 1);
    gemm_softmax_kernel<1><<<grid, 256, SMEM_BYTES>>>(inp, emb, out);
}

// round 4
// speedup vs baseline: 1.3943x; 1.3943x over previous
#include <cuda_runtime.h>
#include <cuda_fp16.h>
#include <cstdint>

#define N_ROWS 4096
#define VOCAB  50000
#define DIM    64

#define BM 128
#define BN 128
#define AS_STRIDE 72   // halves; (row*36 + lc) % 32 distinct for lr 0..7, lc 0..3 -> conflict-free frags

// scratch (no allocs allowed -> device globals)
__device__ float g_sums[N_ROWS];
__device__ float g_loss;
__device__ __half g_A16[N_ROWS * DIM];
__device__ __half g_B16[VOCAB * DIM];

__global__ void init_kernel() {
    int i = blockIdx.x * blockDim.x + threadIdx.x;
    if (i < N_ROWS) g_sums[i] = 0.f;
    if (i == 0) g_loss = 0.f;
}

// convert fp32 inputs/embeddings to fp16 once (fp16 keeps tf32's 10 mantissa bits)
__global__ void convert_kernel(const float* __restrict__ A, const float* __restrict__ B) {
    int i = blockIdx.x * blockDim.x + threadIdx.x;               // float4 index
    const int nA4 = N_ROWS * DIM / 4;                            // 65536
    const int nB4 = VOCAB * DIM / 4;                             // 800000
    if (i < nA4) {
        float4 v = ((const float4*)A)[i];
        __half2* d = (__half2*)g_A16;
        d[i * 2 + 0] = __floats2half2_rn(v.x, v.y);
        d[i * 2 + 1] = __floats2half2_rn(v.z, v.w);
    }
    int j = i - nA4;
    if (j >= 0 && j < nB4) {
        float4 v = ((const float4*)B)[j];
        __half2* d = (__half2*)g_B16;
        d[j * 2 + 0] = __floats2half2_rn(v.x, v.y);
        d[j * 2 + 1] = __floats2half2_rn(v.z, v.w);
    }
}

// PASS 0: logits -> exp -> per-row sums (atomicAdd into g_sums)
// PASS 1: logits -> exp * (1/g_sums[row]) -> write probs
template <int PASS>
__global__ void __launch_bounds__(256, 2)
gemm_softmax_kernel(float* __restrict__ out)        // [N_ROWS, VOCAB]
{
    __shared__ __half As[BM * AS_STRIDE];
    __shared__ __half Bs[BN * AS_STRIDE];

    const int tid = threadIdx.x;
    const int m0 = blockIdx.y * BM;
    const int v0 = blockIdx.x * BN;

    // ---- load fp16 tiles: 128 rows x 64 halves, 8 halves (uint4) per ld ----
    {
        const uint4* Ag = (const uint4*)(g_A16 + (size_t)m0 * DIM);  // 8 uint4 per row
        #pragma unroll
        for (int t = 0; t < 4; t++) {
            int i = tid + t * 256;            // 0..1023
            int row = i >> 3, c8 = i & 7;
            *(uint4*)&As[row * AS_STRIDE + c8 * 8] = Ag[row * 8 + c8];
        }
        #pragma unroll
        for (int t = 0; t < 4; t++) {
            int i = tid + t * 256;
            int row = i >> 3, c8 = i & 7;
            int v = v0 + row;
            uint4 val = make_uint4(0u, 0u, 0u, 0u);
            if (v < VOCAB) val = ((const uint4*)(g_B16 + (size_t)v * DIM))[c8];
            *(uint4*)&Bs[row * AS_STRIDE + c8 * 8] = val;
        }
    }
    __syncthreads();

    const int lane = tid & 31;
    const int wid  = tid >> 5;
    const int wm = wid >> 2;           // 0..1 : 64 rows each
    const int wn = wid & 3;            // 0..3 : 32 cols each
    const int mBase = wm * 64;
    const int nBase = wn * 32;
    const int lr = lane >> 2;          // groupID
    const int lc = lane & 3;           // threadID_in_group

    float c[4][4][4];
    #pragma unroll
    for (int a = 0; a < 4; a++)
        #pragma unroll
        for (int b = 0; b < 4; b++)
            #pragma unroll
            for (int d = 0; d < 4; d++) c[a][b][d] = 0.f;

    // ---- K = 64 = 4 k-steps of m16n8k16 fp16 MMA (fp32 accum) ----
    #pragma unroll
    for (int kk = 0; kk < 4; kk++) {
        unsigned af[4][4], bf[4][2];
        #pragma unroll
        for (int mf = 0; mf < 4; mf++) {
            const __half* base = &As[(mBase + mf * 16 + lr) * AS_STRIDE + kk * 16 + 2 * lc];
            af[mf][0] = *(const unsigned*)(base);
            af[mf][1] = *(const unsigned*)(base + 8 * AS_STRIDE);
            af[mf][2] = *(const unsigned*)(base + 8);
            af[mf][3] = *(const unsigned*)(base + 8 * AS_STRIDE + 8);
        }
        #pragma unroll
        for (int nf = 0; nf < 4; nf++) {
            const __half* base = &Bs[(nBase + nf * 8 + lr) * AS_STRIDE + kk * 16 + 2 * lc];
            bf[nf][0] = *(const unsigned*)(base);
            bf[nf][1] = *(const unsigned*)(base + 8);
        }
        #pragma unroll
        for (int mf = 0; mf < 4; mf++)
            #pragma unroll
            for (int nf = 0; nf < 4; nf++) {
                asm volatile(
                    "mma.sync.aligned.m16n8k16.row.col.f32.f16.f16.f32 "
                    "{%0,%1,%2,%3}, {%4,%5,%6,%7}, {%8,%9}, {%0,%1,%2,%3};"
                    : "+f"(c[mf][nf][0]), "+f"(c[mf][nf][1]),
                      "+f"(c[mf][nf][2]), "+f"(c[mf][nf][3])
                    : "r"(af[mf][0]), "r"(af[mf][1]), "r"(af[mf][2]), "r"(af[mf][3]),
                      "r"(bf[nf][0]), "r"(bf[nf][1]));
            }
    }

    if (PASS == 0) {
        // ---- per-row sum of exp(logit), masked at tail ----
        __syncthreads();
        float* rowsum = (float*)As;           // tiles dead; reuse as BM floats
        if (tid < BM) rowsum[tid] = 0.f;
        __syncthreads();
        #pragma unroll
        for (int mf = 0; mf < 4; mf++) {
            #pragma unroll
            for (int h = 0; h < 2; h++) {
                float s = 0.f;
                #pragma unroll
                for (int nf = 0; nf < 4; nf++) {
                    #pragma unroll
                    for (int j = 0; j < 2; j++) {
                        int col = v0 + nBase + nf * 8 + lc * 2 + j;
                        float e = __expf(c[mf][nf][h * 2 + j]);
                        s += (col < VOCAB) ? e : 0.f;
                    }
                }
                s += __shfl_xor_sync(0xffffffffu, s, 1);
                s += __shfl_xor_sync(0xffffffffu, s, 2);
                if (lc == 0) atomicAdd(&rowsum[mBase + mf * 16 + h * 8 + lr], s);
            }
        }
        __syncthreads();
        if (tid < BM) atomicAdd(&g_sums[m0 + tid], rowsum[tid]);
    } else {
        // ---- write probs = exp(logit) / rowsum; streaming stores keep B16 in L2 ----
        __syncthreads();
        float* inv = (float*)As;
        if (tid < BM) inv[tid] = 1.0f / g_sums[m0 + tid];
        __syncthreads();
        #pragma unroll
        for (int mf = 0; mf < 4; mf++) {
            #pragma unroll
            for (int h = 0; h < 2; h++) {
                int rl = mBase + mf * 16 + h * 8 + lr;
                float r = inv[rl];
                size_t rowOff = (size_t)(m0 + rl) * VOCAB;
                #pragma unroll
                for (int nf = 0; nf < 4; nf++) {
                    int col = v0 + nBase + nf * 8 + lc * 2;
                    if (col < VOCAB) {   // VOCAB even -> pair never straddles the edge
                        float2 p;
                        p.x = __expf(c[mf][nf][h * 2 + 0]) * r;
                        p.y = __expf(c[mf][nf][h * 2 + 1]) * r;
                        __stcs((float2*)(out + rowOff + col), p);
                    }
                }
            }
        }
    }
}

// loss = mean_n( log(sum_n) - logit_label_n ); clipping never binds (min prob ~2e-6 >> 1e-7)
__global__ void loss_kernel(const int* __restrict__ label_words,
                            const float* __restrict__ inp,
                            const float* __restrict__ emb) {
    int n = blockIdx.x * blockDim.x + threadIdx.x;

    // dtype sniff: int64 labels (< 2^31) have all odd 32-bit words == 0
    bool is64 = true;
    #pragma unroll
    for (int i = 0; i < 64; i++) is64 &= (label_words[2 * i + 1] == 0);

    float v = 0.f;
    if (n < N_ROWS) {
        int lab = is64 ? label_words[2 * n] : label_words[n];
        const float4* a = (const float4*)(inp + (size_t)n * DIM);
        const float4* b = (const float4*)(emb + (size_t)lab * DIM);
        float dot = 0.f;
        #pragma unroll
        for (int i = 0; i < DIM / 4; i++) {
            float4 x = a[i], y = b[i];
            dot += x.x * y.x + x.y * y.y + x.z * y.z + x.w * y.w;
        }
        v = logf(g_sums[n]) - dot;
    }
    __shared__ float red[256];
    red[threadIdx.x] = v;
    __syncthreads();
    for (int s = 128; s > 0; s >>= 1) {
        if (threadIdx.x < s) red[threadIdx.x] += red[threadIdx.x + s];
        __syncthreads();
    }
    if (threadIdx.x == 0) atomicAdd(&g_loss, red[0]);
}

__global__ void finalize_kernel(float* out, long long idx) {
    out[idx] = g_loss * (1.0f / (float)N_ROWS);
}

extern "C" void kernel_launch(void* const* d_in, const int* in_sizes, int n_in,
                              void* d_out, int out_size) {
    const int*   label = (const int*)d_in[0];      // int32 or int64 (sniffed in-kernel)
    const float* inp   = (const float*)d_in[1];    // [4096, 64]
    const float* emb   = (const float*)d_in[2];    // [50000, 64]
    float* out = (float*)d_out;                    // [4096*50000] probs + [1] loss

    dim3 grid((VOCAB + BN - 1) / BN, N_ROWS / BM);   // 391 x 32

    init_kernel<<<16, 256>>>();
    convert_kernel<<<(N_ROWS * DIM / 4 + VOCAB * DIM / 4 + 255) / 256, 256>>>(inp, emb);
    gemm_softmax_kernel<0><<<grid, 256>>>(out);
    loss_kernel<<<N_ROWS / 256, 256>>>(label, inp, emb);
    finalize_kernel<<<1, 1>>>(out, (long long)out_size - 1);
    gemm_softmax_kernel<1><<<grid, 256>>>(out);
}